// round 3
// baseline (speedup 1.0000x reference)
#include <cuda_runtime.h>
#include <cuda_fp16.h>
#include <cstdint>
#include <cstddef>

#define HID      512
#define BATCHSZ  65536
#define BM       128
#define BN       128
#define BK       64          // halves per K chunk
#define NK       24          // 1536 / 64
#define STAGES   3
#define NTH      256

// ---------------- fp16 scratch (device globals; no allocation allowed) ----------------
__device__ __align__(16) __half g_x16 [(size_t)BATCHSZ * HID];
__device__ __align__(16) __half g_s16 [(size_t)BATCHSZ * HID];
__device__ __align__(16) __half g_p16 [(size_t)BATCHSZ * HID];
__device__ __align__(16) __half g_hr16[(size_t)BATCHSZ * HID];
__device__ __align__(16) __half g_pr16[(size_t)BATCHSZ * HID];
__device__ __align__(16) __half g_w16 [12 * (size_t)HID * HID];  // [gate(a,r,r1,c)][sec(w,u,p)]
__device__ __align__(16) float  g_att [(size_t)BATCHSZ * HID];

static __device__ __forceinline__ uint32_t smem_u32(const void* p) {
    uint32_t a;
    asm("{ .reg .u64 t; cvta.to.shared.u64 t, %1; cvt.u32.u64 %0, t; }" : "=r"(a) : "l"(p));
    return a;
}
static __device__ __forceinline__ float sigf(float x) {
    return __fdividef(1.0f, 1.0f + __expf(-x));
}
static __device__ __forceinline__ float tanhf_fast(float x) {
    return 1.0f - __fdividef(2.0f, __expf(2.0f * x) + 1.0f);
}

// ---------------- convert kernel ----------------
struct CvtArgs {
    const float* bsrc[3]; __half* bdst[3];     // x, state, parent (8388608 float4 each)
    const float* wsrc[12]; __half* wdst[12];   // 65536 float4 each
};
#define BIG4   8388608u
#define NBIG4  25165824u
#define TOT4   25952256u

__global__ void __launch_bounds__(256) cvt_kernel(CvtArgs a) {
    size_t stride = (size_t)gridDim.x * blockDim.x;
    for (size_t u = (size_t)blockIdx.x * blockDim.x + threadIdx.x; u < TOT4; u += stride) {
        const float4* s;
        __half2* d;
        if (u < NBIG4) {
            int arr = (int)(u / BIG4);
            size_t off = u - (size_t)arr * BIG4;
            s = (const float4*)a.bsrc[arr] + off;
            d = (__half2*)a.bdst[arr] + off * 2;
        } else {
            size_t v = u - NBIG4;
            int idx = (int)(v >> 16);
            size_t off = v & 65535u;
            s = (const float4*)a.wsrc[idx] + off;
            d = (__half2*)a.wdst[idx] + off * 2;
        }
        float4 f = *s;
        __half2 h0 = __floats2half2_rn(f.x, f.y);
        __half2 h1 = __floats2half2_rn(f.z, f.w);
        uint2 pk;
        pk.x = *(uint32_t*)&h0;
        pk.y = *(uint32_t*)&h1;
        *(uint2*)d = pk;
    }
}

// ---------------- GEMM ----------------
struct GArgs {
    const __half* A[3];        // K sections of virtual A
    const __half* B[3][3];     // [gate][sec]
    const float*  bias[3];
    const __half* s16;
    const __half* p16;
    __half* hr16;
    __half* pr16;
    float*  att;
    const float* state_f32;
    float*  out;
};

#define SMEM_BYTES (STAGES * 2 * 16384)

template <int PASS>
__global__ void __launch_bounds__(NTH, 1) gru_gemm(GArgs g) {
    extern __shared__ __align__(16) char sm[];
    const uint32_t smBase = smem_u32(sm);

    const int tid = threadIdx.x;
    const int wid = tid >> 5;
    const int lane = tid & 31;
    const int warp_m = wid >> 2;     // 0..1
    const int warp_n = wid & 3;      // 0..3
    const int m0 = blockIdx.y * BM;

    const int gate = (PASS == 1) ? (blockIdx.x >> 2) : 0;
    const int nInGate = (PASS == 1) ? ((blockIdx.x & 3) * BN) : (blockIdx.x * BN);

    const __half* Asec[3] = { g.A[0], g.A[1], g.A[2] };
    const __half* Bsec[3] = { g.B[gate][0], g.B[gate][1], g.B[gate][2] };

    // cp.async thread mapping (per stage: 1024 16B chunks for A, 1024 for B; 4 each/thread)
    // chunk q: row = q>>3, kc = q&7; swizzled byte off = row*128 + ((kc ^ (row&7))<<4)
    auto issue = [&](int ki, int stage) {
        const int sec = (ki * BK) >> 9;
        const int kin = ki * BK - sec * 512;         // halves
        const __half* Ag = Asec[sec];
        const __half* Bg = Bsec[sec];
        const uint32_t stA = smBase + stage * 16384;
        const uint32_t stB = smBase + STAGES * 16384 + stage * 16384;
#pragma unroll
        for (int i = 0; i < 4; ++i) {
            int q = tid + i * 256;
            int row = q >> 3, kc = q & 7;
            uint32_t soff = (uint32_t)(row * 128 + (((kc ^ (row & 7))) << 4));
            const __half* ga = Ag + (size_t)(m0 + row) * HID + kin + kc * 8;
            asm volatile("cp.async.cg.shared.global [%0], [%1], 16;"
                         :: "r"(stA + soff), "l"(ga));
            const __half* gb = Bg + (size_t)(nInGate + row) * HID + kin + kc * 8;
            asm volatile("cp.async.cg.shared.global [%0], [%1], 16;"
                         :: "r"(stB + soff), "l"(gb));
        }
        asm volatile("cp.async.commit_group;");
    };

    float acc[4][4][4];
#pragma unroll
    for (int a = 0; a < 4; ++a)
#pragma unroll
        for (int b = 0; b < 4; ++b)
#pragma unroll
            for (int c = 0; c < 4; ++c) acc[a][b][c] = 0.0f;

    // ldmatrix lane geometry
    const int rlA = lane & 15;            // A row within 16
    const int khA = lane >> 4;            // A k-half (0/1 -> +8 halves = +1 chunk)
    const int nbo = (lane & 7) + ((lane >> 4) << 3);   // B row within 16
    const int khB = (lane >> 3) & 1;      // B k-half
    const int swA = lane & 7;
    const int swB = nbo & 7;

    issue(0, 0);
    issue(1, 1);

    for (int ki = 0; ki < NK; ++ki) {
        if (ki < NK - 2) asm volatile("cp.async.wait_group 1;");
        else             asm volatile("cp.async.wait_group 0;");
        __syncthreads();
        if (ki + 2 < NK) issue(ki + 2, (ki + 2) % STAGES);

        const int stage = ki % STAGES;
        const uint32_t stA = smBase + stage * 16384;
        const uint32_t stB = smBase + STAGES * 16384 + stage * 16384;
#pragma unroll
        for (int ks = 0; ks < 4; ++ks) {
            uint32_t af[4][4];
            uint32_t bf[2][4];
#pragma unroll
            for (int mt = 0; mt < 4; ++mt) {
                uint32_t addr = stA
                    + (uint32_t)((warp_m * 64 + mt * 16 + rlA) * 128)
                    + (uint32_t)((((ks * 2 + khA) ^ swA)) << 4);
                asm volatile("ldmatrix.sync.aligned.m8n8.x4.shared.b16 {%0,%1,%2,%3}, [%4];"
                             : "=r"(af[mt][0]), "=r"(af[mt][1]), "=r"(af[mt][2]), "=r"(af[mt][3])
                             : "r"(addr));
            }
#pragma unroll
            for (int np = 0; np < 2; ++np) {
                uint32_t addr = stB
                    + (uint32_t)((warp_n * 32 + np * 16 + nbo) * 128)
                    + (uint32_t)((((ks * 2 + khB) ^ swB)) << 4);
                asm volatile("ldmatrix.sync.aligned.m8n8.x4.shared.b16 {%0,%1,%2,%3}, [%4];"
                             : "=r"(bf[np][0]), "=r"(bf[np][1]), "=r"(bf[np][2]), "=r"(bf[np][3])
                             : "r"(addr));
            }
#pragma unroll
            for (int mt = 0; mt < 4; ++mt) {
#pragma unroll
                for (int nt = 0; nt < 4; ++nt) {
                    uint32_t b0 = bf[nt >> 1][(nt & 1) * 2 + 0];
                    uint32_t b1 = bf[nt >> 1][(nt & 1) * 2 + 1];
                    asm volatile(
                        "mma.sync.aligned.m16n8k16.row.col.f32.f16.f16.f32 "
                        "{%0,%1,%2,%3}, {%4,%5,%6,%7}, {%8,%9}, {%0,%1,%2,%3};"
                        : "+f"(acc[mt][nt][0]), "+f"(acc[mt][nt][1]),
                          "+f"(acc[mt][nt][2]), "+f"(acc[mt][nt][3])
                        : "r"(af[mt][0]), "r"(af[mt][1]), "r"(af[mt][2]), "r"(af[mt][3]),
                          "r"(b0), "r"(b1));
                }
            }
        }
    }

    // ---------------- epilogue ----------------
    const int lrow = lane >> 2;
    const int lcol = (lane & 3) * 2;
    const float* biasp = g.bias[gate];

    float bv[4][2];
#pragma unroll
    for (int nt = 0; nt < 4; ++nt) {
        int cg = nInGate + warp_n * 32 + nt * 8 + lcol;
        bv[nt][0] = biasp[cg];
        bv[nt][1] = biasp[cg + 1];
    }

#pragma unroll
    for (int mt = 0; mt < 4; ++mt) {
#pragma unroll
        for (int p = 0; p < 2; ++p) {
            int row = m0 + warp_m * 64 + mt * 16 + lrow + p * 8;
#pragma unroll
            for (int nt = 0; nt < 4; ++nt) {
                int cg = nInGate + warp_n * 32 + nt * 8 + lcol;
                float x0 = acc[mt][nt][p * 2 + 0] + bv[nt][0];
                float x1 = acc[mt][nt][p * 2 + 1] + bv[nt][1];
                size_t idx = (size_t)row * HID + cg;
                if (PASS == 1) {
                    float s0 = sigf(x0), s1 = sigf(x1);
                    if (gate == 0) {
                        float2 o = {s0, s1};
                        *(float2*)&g.att[idx] = o;
                    } else if (gate == 1) {
                        __half2 sv = *(const __half2*)&g.s16[idx];
                        float2 f = __half22float2(sv);
                        *(__half2*)&g.hr16[idx] = __floats2half2_rn(f.x * s0, f.y * s1);
                    } else {
                        __half2 pv = *(const __half2*)&g.p16[idx];
                        float2 f = __half22float2(pv);
                        *(__half2*)&g.pr16[idx] = __floats2half2_rn(f.x * s0, f.y * s1);
                    }
                } else {
                    float c0 = tanhf_fast(x0), c1 = tanhf_fast(x1);
                    float2 a  = *(const float2*)&g.att[idx];
                    float2 st = *(const float2*)&g.state_f32[idx];
                    float2 o;
                    o.x = a.x * c0 + st.x - a.x * st.x;
                    o.y = a.y * c1 + st.y - a.y * st.y;
                    *(float2*)&g.out[idx] = o;
                }
            }
        }
    }
}

extern "C" void kernel_launch(void* const* d_in, const int* in_sizes, int n_in,
                              void* d_out, int out_size) {
    const float* inputs = (const float*)d_in[0];
    const float* state  = (const float*)d_in[1];
    const float* parent = (const float*)d_in[2];
    // weights: w_a(3), w_a_b(4), w_r(5), w_r_b(6), w_r1(7), w_r1_b(8), w_c(9), w_c_b(10),
    //          u_a(11), u_r(12), u_r1(13), u_c(14), p_a(15), p_r(16), p_r1(17), p_c(18)

    void *px16, *ps16, *pp16, *phr, *ppr, *pw16, *patt;
    cudaGetSymbolAddress(&px16, g_x16);
    cudaGetSymbolAddress(&ps16, g_s16);
    cudaGetSymbolAddress(&pp16, g_p16);
    cudaGetSymbolAddress(&phr,  g_hr16);
    cudaGetSymbolAddress(&ppr,  g_pr16);
    cudaGetSymbolAddress(&pw16, g_w16);
    cudaGetSymbolAddress(&patt, g_att);

    __half* w16 = (__half*)pw16;
    const size_t WSZ = (size_t)HID * HID;

    CvtArgs ca;
    ca.bsrc[0] = inputs; ca.bdst[0] = (__half*)px16;
    ca.bsrc[1] = state;  ca.bdst[1] = (__half*)ps16;
    ca.bsrc[2] = parent; ca.bdst[2] = (__half*)pp16;
    // gate order a,r,r1,c ; sec order w,u,p
    const int wIdx[4] = {3, 5, 7, 9};     // w_*_w
    const int uIdx[4] = {11, 12, 13, 14}; // u_*
    const int pIdx[4] = {15, 16, 17, 18}; // p_*
    for (int gg = 0; gg < 4; ++gg) {
        ca.wsrc[gg * 3 + 0] = (const float*)d_in[wIdx[gg]];
        ca.wsrc[gg * 3 + 1] = (const float*)d_in[uIdx[gg]];
        ca.wsrc[gg * 3 + 2] = (const float*)d_in[pIdx[gg]];
        for (int s = 0; s < 3; ++s)
            ca.wdst[gg * 3 + s] = w16 + (size_t)(gg * 3 + s) * WSZ;
    }

    cudaFuncSetAttribute(gru_gemm<1>, cudaFuncAttributeMaxDynamicSharedMemorySize, SMEM_BYTES);
    cudaFuncSetAttribute(gru_gemm<2>, cudaFuncAttributeMaxDynamicSharedMemorySize, SMEM_BYTES);

    GArgs a1 = {};
    a1.A[0] = (const __half*)px16; a1.A[1] = (const __half*)ps16; a1.A[2] = (const __half*)pp16;
    for (int gg = 0; gg < 3; ++gg)
        for (int s = 0; s < 3; ++s)
            a1.B[gg][s] = w16 + (size_t)(gg * 3 + s) * WSZ;
    a1.bias[0] = (const float*)d_in[4];
    a1.bias[1] = (const float*)d_in[6];
    a1.bias[2] = (const float*)d_in[8];
    a1.s16 = (const __half*)ps16;
    a1.p16 = (const __half*)pp16;
    a1.hr16 = (__half*)phr;
    a1.pr16 = (__half*)ppr;
    a1.att = (float*)patt;
    a1.state_f32 = state;
    a1.out = nullptr;

    GArgs a2 = {};
    a2.A[0] = (const __half*)px16; a2.A[1] = (const __half*)phr; a2.A[2] = (const __half*)ppr;
    for (int s = 0; s < 3; ++s) {
        a2.B[0][s] = w16 + (size_t)(9 + s) * WSZ;
        a2.B[1][s] = a2.B[0][s];
        a2.B[2][s] = a2.B[0][s];
    }
    a2.bias[0] = (const float*)d_in[10];
    a2.bias[1] = a2.bias[0];
    a2.bias[2] = a2.bias[0];
    a2.s16 = (const __half*)ps16;
    a2.p16 = (const __half*)pp16;
    a2.hr16 = (__half*)phr;
    a2.pr16 = (__half*)ppr;
    a2.att = (float*)patt;
    a2.state_f32 = state;
    a2.out = (float*)d_out;

    cvt_kernel<<<8192, 256>>>(ca);
    gru_gemm<1><<<dim3(12, BATCHSZ / BM), NTH, SMEM_BYTES>>>(a1);
    gru_gemm<2><<<dim3(4,  BATCHSZ / BM), NTH, SMEM_BYTES>>>(a2);
}

// round 6
// speedup vs baseline: 1.0617x; 1.0617x over previous
#include <cuda_runtime.h>
#include <cuda_fp16.h>
#include <cstdint>
#include <cstddef>

#define HID      512
#define BATCHSZ  65536
#define BM       256
#define BN       128
#define BK       64          // halves per K chunk
#define NK       24          // 1536 / 64
#define STAGES   4
#define NTH      256

// ---------------- fp16 scratch (device globals; no allocation allowed) ----------------
__device__ __align__(16) __half g_x16 [(size_t)BATCHSZ * HID];
__device__ __align__(16) __half g_s16 [(size_t)BATCHSZ * HID];
__device__ __align__(16) __half g_p16 [(size_t)BATCHSZ * HID];
__device__ __align__(16) __half g_hr16[(size_t)BATCHSZ * HID];
__device__ __align__(16) __half g_pr16[(size_t)BATCHSZ * HID];
__device__ __align__(16) __half g_w16 [12 * (size_t)HID * HID];  // [gate(a,r,r1,c)][sec(w,u,p)]
__device__ __align__(16) float  g_att [(size_t)BATCHSZ * HID];

static __device__ __forceinline__ uint32_t smem_u32(const void* p) {
    uint32_t a;
    asm("{ .reg .u64 t; cvta.to.shared.u64 t, %1; cvt.u32.u64 %0, t; }" : "=r"(a) : "l"(p));
    return a;
}
static __device__ __forceinline__ float sigf(float x) {
    return __fdividef(1.0f, 1.0f + __expf(-x));
}
static __device__ __forceinline__ float tanhf_fast(float x) {
    return 1.0f - __fdividef(2.0f, __expf(2.0f * x) + 1.0f);
}

// ---------------- convert kernels (split for ncu launch-alignment) ----------------
struct CvtW {
    const float* src[12];
    __half* dst[12];
};
__global__ void __launch_bounds__(256) cvt_w_kernel(CvtW a) {
    // 12 * 65536 float4 chunks
    size_t stride = (size_t)gridDim.x * blockDim.x;
    for (size_t u = (size_t)blockIdx.x * blockDim.x + threadIdx.x; u < 786432u; u += stride) {
        int idx = (int)(u >> 16);
        size_t off = u & 65535u;
        float4 f = *((const float4*)a.src[idx] + off);
        __half2 h0 = __floats2half2_rn(f.x, f.y);
        __half2 h1 = __floats2half2_rn(f.z, f.w);
        uint2 pk = { *(uint32_t*)&h0, *(uint32_t*)&h1 };
        *((uint2*)a.dst[idx] + off) = pk;
    }
}
struct CvtB {
    const float* src[3];
    __half* dst[3];
};
#define BIG4 8388608u
__global__ void __launch_bounds__(256) cvt_b_kernel(CvtB a) {
    size_t stride = (size_t)gridDim.x * blockDim.x;
    for (size_t u = (size_t)blockIdx.x * blockDim.x + threadIdx.x; u < 3u * BIG4; u += stride) {
        int arr = (int)(u / BIG4);
        size_t off = u - (size_t)arr * BIG4;
        float4 f = *((const float4*)a.src[arr] + off);
        __half2 h0 = __floats2half2_rn(f.x, f.y);
        __half2 h1 = __floats2half2_rn(f.z, f.w);
        uint2 pk = { *(uint32_t*)&h0, *(uint32_t*)&h1 };
        *((uint2*)a.dst[arr] + off) = pk;
    }
}

// ---------------- GEMM ----------------
struct GArgs {
    const __half* A[3];        // K sections of virtual A
    const __half* B[3][3];     // [gate][sec]
    const float*  bias[3];
    const __half* s16;
    const __half* p16;
    __half* hr16;
    __half* pr16;
    float*  att;
    const float* state_f32;
    float*  out;
};

// smem: A stages [0, 4*32768), B stages [131072, 131072 + 4*16384)
#define SMEM_BYTES (STAGES * (32768 + 16384))

template <int PASS>
__global__ void __launch_bounds__(NTH, 1) gru_gemm(GArgs g) {
    extern __shared__ __align__(16) char sm[];
    const uint32_t smBase = smem_u32(sm);

    const int tid = threadIdx.x;
    const int wid = tid >> 5;
    const int lane = tid & 31;
    const int warp_m = wid & 3;      // 0..3 -> 64-row slice
    const int warp_n = wid >> 2;     // 0..1 -> 64-col slice
    const int m0 = blockIdx.y * BM;

    const int gate = (PASS == 1) ? (blockIdx.x >> 2) : 0;
    const int nInGate = (PASS == 1) ? ((blockIdx.x & 3) * BN) : (blockIdx.x * BN);

    const __half* Asec[3] = { g.A[0], g.A[1], g.A[2] };
    const __half* Bsec[3] = { g.B[gate][0], g.B[gate][1], g.B[gate][2] };

    // per stage: A 2048 16B chunks (256 rows x 8), B 1024 chunks (128 rows x 8)
    auto issue = [&](int ki, int stage) {
        const int sec = (ki * BK) >> 9;
        const int kin = ki * BK - sec * 512;         // halves
        const __half* Ag = Asec[sec];
        const __half* Bg = Bsec[sec];
        const uint32_t stA = smBase + stage * 32768;
        const uint32_t stB = smBase + STAGES * 32768 + stage * 16384;
#pragma unroll
        for (int i = 0; i < 12; ++i) {
            int q = tid + i * 256;
            if (q < 2048) {
                int row = q >> 3, kc = q & 7;
                uint32_t soff = (uint32_t)(row * 128 + ((kc ^ (row & 7)) << 4));
                const __half* ga = Ag + (size_t)(m0 + row) * HID + kin + kc * 8;
                asm volatile("cp.async.cg.shared.global [%0], [%1], 16;"
                             :: "r"(stA + soff), "l"(ga));
            } else {
                int qq = q - 2048;
                int row = qq >> 3, kc = qq & 7;
                uint32_t soff = (uint32_t)(row * 128 + ((kc ^ (row & 7)) << 4));
                const __half* gb = Bg + (size_t)(nInGate + row) * HID + kin + kc * 8;
                asm volatile("cp.async.cg.shared.global [%0], [%1], 16;"
                             :: "r"(stB + soff), "l"(gb));
            }
        }
        asm volatile("cp.async.commit_group;");
    };

    float acc[4][8][4];
#pragma unroll
    for (int a = 0; a < 4; ++a)
#pragma unroll
        for (int b = 0; b < 8; ++b)
#pragma unroll
            for (int c = 0; c < 4; ++c) acc[a][b][c] = 0.0f;

    // ldmatrix lane geometry (validated in round-3 kernel)
    const int rlA = lane & 15;
    const int khA = lane >> 4;
    const int nbo = (lane & 7) + ((lane >> 4) << 3);
    const int khB = (lane >> 3) & 1;
    const int swA = lane & 7;
    const int swB = nbo & 7;

    issue(0, 0);
    issue(1, 1);
    issue(2, 2);

    for (int ki = 0; ki < NK; ++ki) {
        if (ki < NK - 2)      asm volatile("cp.async.wait_group 2;");
        else if (ki == NK - 2) asm volatile("cp.async.wait_group 1;");
        else                  asm volatile("cp.async.wait_group 0;");
        __syncthreads();
        if (ki + 3 < NK) issue(ki + 3, (ki + 3) % STAGES);

        const int stage = ki % STAGES;
        const uint32_t stA = smBase + stage * 32768;
        const uint32_t stB = smBase + STAGES * 32768 + stage * 16384;
#pragma unroll
        for (int ks = 0; ks < 4; ++ks) {
            uint32_t af[4][4];
            uint32_t bf[4][4];
#pragma unroll
            for (int mt = 0; mt < 4; ++mt) {
                uint32_t addr = stA
                    + (uint32_t)((warp_m * 64 + mt * 16 + rlA) * 128)
                    + (uint32_t)(((ks * 2 + khA) ^ swA) << 4);
                asm volatile("ldmatrix.sync.aligned.m8n8.x4.shared.b16 {%0,%1,%2,%3}, [%4];"
                             : "=r"(af[mt][0]), "=r"(af[mt][1]), "=r"(af[mt][2]), "=r"(af[mt][3])
                             : "r"(addr));
            }
#pragma unroll
            for (int np = 0; np < 4; ++np) {
                uint32_t addr = stB
                    + (uint32_t)((warp_n * 64 + np * 16 + nbo) * 128)
                    + (uint32_t)(((ks * 2 + khB) ^ swB) << 4);
                asm volatile("ldmatrix.sync.aligned.m8n8.x4.shared.b16 {%0,%1,%2,%3}, [%4];"
                             : "=r"(bf[np][0]), "=r"(bf[np][1]), "=r"(bf[np][2]), "=r"(bf[np][3])
                             : "r"(addr));
            }
#pragma unroll
            for (int mt = 0; mt < 4; ++mt) {
#pragma unroll
                for (int nt = 0; nt < 8; ++nt) {
                    uint32_t b0 = bf[nt >> 1][(nt & 1) * 2 + 0];
                    uint32_t b1 = bf[nt >> 1][(nt & 1) * 2 + 1];
                    asm volatile(
                        "mma.sync.aligned.m16n8k16.row.col.f32.f16.f16.f32 "
                        "{%0,%1,%2,%3}, {%4,%5,%6,%7}, {%8,%9}, {%0,%1,%2,%3};"
                        : "+f"(acc[mt][nt][0]), "+f"(acc[mt][nt][1]),
                          "+f"(acc[mt][nt][2]), "+f"(acc[mt][nt][3])
                        : "r"(af[mt][0]), "r"(af[mt][1]), "r"(af[mt][2]), "r"(af[mt][3]),
                          "r"(b0), "r"(b1));
                }
            }
        }
    }

    // ---------------- epilogue ----------------
    const int lrow = lane >> 2;
    const int lcol = (lane & 3) * 2;
    const float* biasp = g.bias[gate];

    float bv[8][2];
#pragma unroll
    for (int nt = 0; nt < 8; ++nt) {
        int cg = nInGate + warp_n * 64 + nt * 8 + lcol;
        bv[nt][0] = biasp[cg];
        bv[nt][1] = biasp[cg + 1];
    }

#pragma unroll
    for (int mt = 0; mt < 4; ++mt) {
#pragma unroll
        for (int p = 0; p < 2; ++p) {
            int row = m0 + warp_m * 64 + mt * 16 + lrow + p * 8;
#pragma unroll
            for (int nt = 0; nt < 8; ++nt) {
                int cg = nInGate + warp_n * 64 + nt * 8 + lcol;
                float x0 = acc[mt][nt][p * 2 + 0] + bv[nt][0];
                float x1 = acc[mt][nt][p * 2 + 1] + bv[nt][1];
                size_t idx = (size_t)row * HID + cg;
                if (PASS == 1) {
                    float s0 = sigf(x0), s1 = sigf(x1);
                    if (gate == 0) {
                        float2 o = {s0, s1};
                        *(float2*)&g.att[idx] = o;
                    } else if (gate == 1) {
                        __half2 sv = *(const __half2*)&g.s16[idx];
                        float2 f = __half22float2(sv);
                        *(__half2*)&g.hr16[idx] = __floats2half2_rn(f.x * s0, f.y * s1);
                    } else {
                        __half2 pv = *(const __half2*)&g.p16[idx];
                        float2 f = __half22float2(pv);
                        *(__half2*)&g.pr16[idx] = __floats2half2_rn(f.x * s0, f.y * s1);
                    }
                } else {
                    float c0 = tanhf_fast(x0), c1 = tanhf_fast(x1);
                    float2 a  = *(const float2*)&g.att[idx];
                    float2 st = *(const float2*)&g.state_f32[idx];
                    float2 o;
                    o.x = a.x * c0 + st.x - a.x * st.x;
                    o.y = a.y * c1 + st.y - a.y * st.y;
                    *(float2*)&g.out[idx] = o;
                }
            }
        }
    }
}

extern "C" void kernel_launch(void* const* d_in, const int* in_sizes, int n_in,
                              void* d_out, int out_size) {
    const float* inputs = (const float*)d_in[0];
    const float* state  = (const float*)d_in[1];
    const float* parent = (const float*)d_in[2];

    void *px16, *ps16, *pp16, *phr, *ppr, *pw16, *patt;
    cudaGetSymbolAddress(&px16, g_x16);
    cudaGetSymbolAddress(&ps16, g_s16);
    cudaGetSymbolAddress(&pp16, g_p16);
    cudaGetSymbolAddress(&phr,  g_hr16);
    cudaGetSymbolAddress(&ppr,  g_pr16);
    cudaGetSymbolAddress(&pw16, g_w16);
    cudaGetSymbolAddress(&patt, g_att);

    __half* w16 = (__half*)pw16;
    const size_t WSZ = (size_t)HID * HID;

    // gate order a,r,r1,c ; sec order w,u,p
    const int wIdx[4] = {3, 5, 7, 9};
    const int uIdx[4] = {11, 12, 13, 14};
    const int pIdx[4] = {15, 16, 17, 18};

    CvtW cw;
    for (int gg = 0; gg < 4; ++gg) {
        cw.src[gg * 3 + 0] = (const float*)d_in[wIdx[gg]];
        cw.src[gg * 3 + 1] = (const float*)d_in[uIdx[gg]];
        cw.src[gg * 3 + 2] = (const float*)d_in[pIdx[gg]];
        for (int s = 0; s < 3; ++s)
            cw.dst[gg * 3 + s] = w16 + (size_t)(gg * 3 + s) * WSZ;
    }
    CvtB cb;
    cb.src[0] = inputs; cb.dst[0] = (__half*)px16;
    cb.src[1] = state;  cb.dst[1] = (__half*)ps16;
    cb.src[2] = parent; cb.dst[2] = (__half*)pp16;

    cudaFuncSetAttribute(gru_gemm<1>, cudaFuncAttributeMaxDynamicSharedMemorySize, SMEM_BYTES);
    cudaFuncSetAttribute(gru_gemm<2>, cudaFuncAttributeMaxDynamicSharedMemorySize, SMEM_BYTES);

    GArgs a1 = {};
    a1.A[0] = (const __half*)px16; a1.A[1] = (const __half*)ps16; a1.A[2] = (const __half*)pp16;
    for (int gg = 0; gg < 3; ++gg)
        for (int s = 0; s < 3; ++s)
            a1.B[gg][s] = w16 + (size_t)(gg * 3 + s) * WSZ;
    a1.bias[0] = (const float*)d_in[4];
    a1.bias[1] = (const float*)d_in[6];
    a1.bias[2] = (const float*)d_in[8];
    a1.s16 = (const __half*)ps16;
    a1.p16 = (const __half*)pp16;
    a1.hr16 = (__half*)phr;
    a1.pr16 = (__half*)ppr;
    a1.att = (float*)patt;
    a1.state_f32 = state;
    a1.out = nullptr;

    GArgs a2 = {};
    a2.A[0] = (const __half*)px16; a2.A[1] = (const __half*)phr; a2.A[2] = (const __half*)ppr;
    for (int s = 0; s < 3; ++s) {
        a2.B[0][s] = w16 + (size_t)(9 + s) * WSZ;
        a2.B[1][s] = a2.B[0][s];
        a2.B[2][s] = a2.B[0][s];
    }
    a2.bias[0] = (const float*)d_in[10];
    a2.bias[1] = a2.bias[0];
    a2.bias[2] = a2.bias[0];
    a2.s16 = (const __half*)ps16;
    a2.p16 = (const __half*)pp16;
    a2.hr16 = (__half*)phr;
    a2.pr16 = (__half*)ppr;
    a2.att = (float*)patt;
    a2.state_f32 = state;
    a2.out = (float*)d_out;

    cvt_w_kernel<<<768, 256>>>(cw);
    cvt_b_kernel<<<8192, 256>>>(cb);
    // Pass 1: gates a, r, r1  (12 N-bands of 128 over 1536 outputs, x-major for L2 reuse of A)
    gru_gemm<1><<<dim3(12, BATCHSZ / BM), NTH, SMEM_BYTES>>>(a1);
    // Pass 2: gate c + final blend
    gru_gemm<2><<<dim3(4,  BATCHSZ / BM), NTH, SMEM_BYTES>>>(a2);
}

// round 7
// speedup vs baseline: 1.2321x; 1.1605x over previous
#include <cuda_runtime.h>
#include <cuda_fp16.h>
#include <cstdint>
#include <cstddef>

#define HID      512
#define BATCHSZ  65536
#define BM       256
#define BN       128
#define BK       64          // halves per K chunk
#define NK       24          // 1536 / 64
#define STAGES   4
#define NTH      512

// ---------------- fp16 scratch (device globals; no allocation allowed) ----------------
__device__ __align__(16) __half g_x16 [(size_t)BATCHSZ * HID];
__device__ __align__(16) __half g_s16 [(size_t)BATCHSZ * HID];
__device__ __align__(16) __half g_p16 [(size_t)BATCHSZ * HID];
__device__ __align__(16) __half g_hr16[(size_t)BATCHSZ * HID];
__device__ __align__(16) __half g_pr16[(size_t)BATCHSZ * HID];
__device__ __align__(16) __half g_w16 [12 * (size_t)HID * HID];  // [gate(a,r,r1,c)][sec(w,u,p)]
__device__ __align__(16) __half g_att [(size_t)BATCHSZ * HID];   // att gate, fp16

static __device__ __forceinline__ uint32_t smem_u32(const void* p) {
    uint32_t a;
    asm("{ .reg .u64 t; cvta.to.shared.u64 t, %1; cvt.u32.u64 %0, t; }" : "=r"(a) : "l"(p));
    return a;
}
static __device__ __forceinline__ float sigf(float x) {
    return __fdividef(1.0f, 1.0f + __expf(-x));
}
static __device__ __forceinline__ float tanhf_fast(float x) {
    return 1.0f - __fdividef(2.0f, __expf(2.0f * x) + 1.0f);
}

// ---------------- convert kernels ----------------
struct CvtW {
    const float* src[12];
    __half* dst[12];
};
__global__ void __launch_bounds__(256) cvt_w_kernel(CvtW a) {
    size_t stride = (size_t)gridDim.x * blockDim.x;
    for (size_t u = (size_t)blockIdx.x * blockDim.x + threadIdx.x; u < 786432u; u += stride) {
        int idx = (int)(u >> 16);
        size_t off = u & 65535u;
        float4 f = *((const float4*)a.src[idx] + off);
        __half2 h0 = __floats2half2_rn(f.x, f.y);
        __half2 h1 = __floats2half2_rn(f.z, f.w);
        uint2 pk = { *(uint32_t*)&h0, *(uint32_t*)&h1 };
        *((uint2*)a.dst[idx] + off) = pk;
    }
}
struct CvtB {
    const float* src[3];
    __half* dst[3];
};
#define BIG4 8388608u
__global__ void __launch_bounds__(256) cvt_b_kernel(CvtB a) {
    size_t stride = (size_t)gridDim.x * blockDim.x;
    for (size_t u = (size_t)blockIdx.x * blockDim.x + threadIdx.x; u < 3u * BIG4; u += stride) {
        int arr = (int)(u / BIG4);
        size_t off = u - (size_t)arr * BIG4;
        float4 f = *((const float4*)a.src[arr] + off);
        __half2 h0 = __floats2half2_rn(f.x, f.y);
        __half2 h1 = __floats2half2_rn(f.z, f.w);
        uint2 pk = { *(uint32_t*)&h0, *(uint32_t*)&h1 };
        *((uint2*)a.dst[arr] + off) = pk;
    }
}

// ---------------- GEMM ----------------
struct GArgs {
    const __half* A[3];        // K sections of virtual A
    const __half* B[3][3];     // [gate][sec]
    const float*  bias[3];
    const __half* s16;
    const __half* p16;
    __half* hr16;
    __half* pr16;
    __half* att;
    const float* state_f32;
    float*  out;
};

// smem: A stages [0, 4*32768), B stages [131072, 131072 + 4*16384)
#define SMEM_BYTES (STAGES * (32768 + 16384))

template <int PASS>
__global__ void __launch_bounds__(NTH, 1) gru_gemm(GArgs g) {
    extern __shared__ __align__(16) char sm[];
    const uint32_t smBase = smem_u32(sm);

    const int tid = threadIdx.x;
    const int wid = tid >> 5;
    const int lane = tid & 31;
    const int warp_m = wid & 3;      // 0..3 -> 64-row slice
    const int warp_n = wid >> 2;     // 0..3 -> 32-col slice
    const int m0 = blockIdx.y * BM;

    const int gate = (PASS == 1) ? (blockIdx.x >> 2) : 0;
    const int nInGate = (PASS == 1) ? ((blockIdx.x & 3) * BN) : (blockIdx.x * BN);

    const __half* Asec[3] = { g.A[0], g.A[1], g.A[2] };
    const __half* Bsec[3] = { g.B[gate][0], g.B[gate][1], g.B[gate][2] };

    // per stage: A 2048 16B chunks (256 rows x 8), B 1024 chunks (128 rows x 8); 6/thread
    auto issue = [&](int ki, int stage) {
        const int sec = (ki * BK) >> 9;
        const int kin = ki * BK - sec * 512;         // halves
        const __half* Ag = Asec[sec];
        const __half* Bg = Bsec[sec];
        const uint32_t stA = smBase + stage * 32768;
        const uint32_t stB = smBase + STAGES * 32768 + stage * 16384;
#pragma unroll
        for (int i = 0; i < 6; ++i) {
            int q = tid + i * 512;
            if (q < 2048) {
                int row = q >> 3, kc = q & 7;
                uint32_t soff = (uint32_t)(row * 128 + ((kc ^ (row & 7)) << 4));
                const __half* ga = Ag + (size_t)(m0 + row) * HID + kin + kc * 8;
                asm volatile("cp.async.cg.shared.global [%0], [%1], 16;"
                             :: "r"(stA + soff), "l"(ga));
            } else {
                int qq = q - 2048;
                int row = qq >> 3, kc = qq & 7;
                uint32_t soff = (uint32_t)(row * 128 + ((kc ^ (row & 7)) << 4));
                const __half* gb = Bg + (size_t)(nInGate + row) * HID + kin + kc * 8;
                asm volatile("cp.async.cg.shared.global [%0], [%1], 16;"
                             :: "r"(stB + soff), "l"(gb));
            }
        }
        asm volatile("cp.async.commit_group;");
    };

    float acc[4][4][4];
#pragma unroll
    for (int a = 0; a < 4; ++a)
#pragma unroll
        for (int b = 0; b < 4; ++b)
#pragma unroll
            for (int c = 0; c < 4; ++c) acc[a][b][c] = 0.0f;

    // ldmatrix lane geometry (validated)
    const int rlA = lane & 15;
    const int khA = lane >> 4;
    const int nbo = (lane & 7) + ((lane >> 4) << 3);
    const int khB = (lane >> 3) & 1;
    const int swA = lane & 7;
    const int swB = nbo & 7;

    issue(0, 0);
    issue(1, 1);
    issue(2, 2);

    for (int ki = 0; ki < NK; ++ki) {
        if (ki < NK - 2)      asm volatile("cp.async.wait_group 2;");
        else if (ki == NK - 2) asm volatile("cp.async.wait_group 1;");
        else                  asm volatile("cp.async.wait_group 0;");
        __syncthreads();
        if (ki + 3 < NK) issue(ki + 3, (ki + 3) % STAGES);

        const int stage = ki % STAGES;
        const uint32_t stA = smBase + stage * 32768;
        const uint32_t stB = smBase + STAGES * 32768 + stage * 16384;
#pragma unroll
        for (int ks = 0; ks < 4; ++ks) {
            uint32_t af[4][4];
            uint32_t bf[2][4];
#pragma unroll
            for (int mt = 0; mt < 4; ++mt) {
                uint32_t addr = stA
                    + (uint32_t)((warp_m * 64 + mt * 16 + rlA) * 128)
                    + (uint32_t)(((ks * 2 + khA) ^ swA) << 4);
                asm volatile("ldmatrix.sync.aligned.m8n8.x4.shared.b16 {%0,%1,%2,%3}, [%4];"
                             : "=r"(af[mt][0]), "=r"(af[mt][1]), "=r"(af[mt][2]), "=r"(af[mt][3])
                             : "r"(addr));
            }
#pragma unroll
            for (int np = 0; np < 2; ++np) {
                uint32_t addr = stB
                    + (uint32_t)((warp_n * 32 + np * 16 + nbo) * 128)
                    + (uint32_t)(((ks * 2 + khB) ^ swB) << 4);
                asm volatile("ldmatrix.sync.aligned.m8n8.x4.shared.b16 {%0,%1,%2,%3}, [%4];"
                             : "=r"(bf[np][0]), "=r"(bf[np][1]), "=r"(bf[np][2]), "=r"(bf[np][3])
                             : "r"(addr));
            }
#pragma unroll
            for (int mt = 0; mt < 4; ++mt) {
#pragma unroll
                for (int nt = 0; nt < 4; ++nt) {
                    uint32_t b0 = bf[nt >> 1][(nt & 1) * 2 + 0];
                    uint32_t b1 = bf[nt >> 1][(nt & 1) * 2 + 1];
                    asm volatile(
                        "mma.sync.aligned.m16n8k16.row.col.f32.f16.f16.f32 "
                        "{%0,%1,%2,%3}, {%4,%5,%6,%7}, {%8,%9}, {%0,%1,%2,%3};"
                        : "+f"(acc[mt][nt][0]), "+f"(acc[mt][nt][1]),
                          "+f"(acc[mt][nt][2]), "+f"(acc[mt][nt][3])
                        : "r"(af[mt][0]), "r"(af[mt][1]), "r"(af[mt][2]), "r"(af[mt][3]),
                          "r"(b0), "r"(b1));
                }
            }
        }
    }

    // ---------------- epilogue ----------------
    const int lrow = lane >> 2;
    const int lcol = (lane & 3) * 2;
    const float* biasp = g.bias[gate];

    float bv[4][2];
#pragma unroll
    for (int nt = 0; nt < 4; ++nt) {
        int cg = nInGate + warp_n * 32 + nt * 8 + lcol;
        bv[nt][0] = biasp[cg];
        bv[nt][1] = biasp[cg + 1];
    }

#pragma unroll
    for (int mt = 0; mt < 4; ++mt) {
#pragma unroll
        for (int p = 0; p < 2; ++p) {
            int row = m0 + warp_m * 64 + mt * 16 + lrow + p * 8;
#pragma unroll
            for (int nt = 0; nt < 4; ++nt) {
                int cg = nInGate + warp_n * 32 + nt * 8 + lcol;
                float x0 = acc[mt][nt][p * 2 + 0] + bv[nt][0];
                float x1 = acc[mt][nt][p * 2 + 1] + bv[nt][1];
                size_t idx = (size_t)row * HID + cg;
                if (PASS == 1) {
                    float s0 = sigf(x0), s1 = sigf(x1);
                    if (gate == 0) {
                        *(__half2*)&g.att[idx] = __floats2half2_rn(s0, s1);
                    } else if (gate == 1) {
                        __half2 sv = *(const __half2*)&g.s16[idx];
                        float2 f = __half22float2(sv);
                        *(__half2*)&g.hr16[idx] = __floats2half2_rn(f.x * s0, f.y * s1);
                    } else {
                        __half2 pv = *(const __half2*)&g.p16[idx];
                        float2 f = __half22float2(pv);
                        *(__half2*)&g.pr16[idx] = __floats2half2_rn(f.x * s0, f.y * s1);
                    }
                } else {
                    float c0 = tanhf_fast(x0), c1 = tanhf_fast(x1);
                    __half2 ah = *(const __half2*)&g.att[idx];
                    float2 a = __half22float2(ah);
                    float2 st = *(const float2*)&g.state_f32[idx];
                    float2 o;
                    o.x = a.x * c0 + st.x - a.x * st.x;
                    o.y = a.y * c1 + st.y - a.y * st.y;
                    *(float2*)&g.out[idx] = o;
                }
            }
        }
    }
}

extern "C" void kernel_launch(void* const* d_in, const int* in_sizes, int n_in,
                              void* d_out, int out_size) {
    const float* inputs = (const float*)d_in[0];
    const float* state  = (const float*)d_in[1];
    const float* parent = (const float*)d_in[2];

    void *px16, *ps16, *pp16, *phr, *ppr, *pw16, *patt;
    cudaGetSymbolAddress(&px16, g_x16);
    cudaGetSymbolAddress(&ps16, g_s16);
    cudaGetSymbolAddress(&pp16, g_p16);
    cudaGetSymbolAddress(&phr,  g_hr16);
    cudaGetSymbolAddress(&ppr,  g_pr16);
    cudaGetSymbolAddress(&pw16, g_w16);
    cudaGetSymbolAddress(&patt, g_att);

    __half* w16 = (__half*)pw16;
    const size_t WSZ = (size_t)HID * HID;

    // gate order a,r,r1,c ; sec order w,u,p
    const int wIdx[4] = {3, 5, 7, 9};
    const int uIdx[4] = {11, 12, 13, 14};
    const int pIdx[4] = {15, 16, 17, 18};

    CvtW cw;
    for (int gg = 0; gg < 4; ++gg) {
        cw.src[gg * 3 + 0] = (const float*)d_in[wIdx[gg]];
        cw.src[gg * 3 + 1] = (const float*)d_in[uIdx[gg]];
        cw.src[gg * 3 + 2] = (const float*)d_in[pIdx[gg]];
        for (int s = 0; s < 3; ++s)
            cw.dst[gg * 3 + s] = w16 + (size_t)(gg * 3 + s) * WSZ;
    }
    CvtB cb;
    cb.src[0] = inputs; cb.dst[0] = (__half*)px16;
    cb.src[1] = state;  cb.dst[1] = (__half*)ps16;
    cb.src[2] = parent; cb.dst[2] = (__half*)pp16;

    cudaFuncSetAttribute(gru_gemm<1>, cudaFuncAttributeMaxDynamicSharedMemorySize, SMEM_BYTES);
    cudaFuncSetAttribute(gru_gemm<2>, cudaFuncAttributeMaxDynamicSharedMemorySize, SMEM_BYTES);

    GArgs a1 = {};
    a1.A[0] = (const __half*)px16; a1.A[1] = (const __half*)ps16; a1.A[2] = (const __half*)pp16;
    for (int gg = 0; gg < 3; ++gg)
        for (int s = 0; s < 3; ++s)
            a1.B[gg][s] = w16 + (size_t)(gg * 3 + s) * WSZ;
    a1.bias[0] = (const float*)d_in[4];
    a1.bias[1] = (const float*)d_in[6];
    a1.bias[2] = (const float*)d_in[8];
    a1.s16 = (const __half*)ps16;
    a1.p16 = (const __half*)pp16;
    a1.hr16 = (__half*)phr;
    a1.pr16 = (__half*)ppr;
    a1.att = (__half*)patt;
    a1.state_f32 = state;
    a1.out = nullptr;

    GArgs a2 = {};
    a2.A[0] = (const __half*)px16; a2.A[1] = (const __half*)phr; a2.A[2] = (const __half*)ppr;
    for (int s = 0; s < 3; ++s) {
        a2.B[0][s] = w16 + (size_t)(9 + s) * WSZ;
        a2.B[1][s] = a2.B[0][s];
        a2.B[2][s] = a2.B[0][s];
    }
    a2.bias[0] = (const float*)d_in[10];
    a2.bias[1] = a2.bias[0];
    a2.bias[2] = a2.bias[0];
    a2.s16 = (const __half*)ps16;
    a2.p16 = (const __half*)pp16;
    a2.hr16 = (__half*)phr;
    a2.pr16 = (__half*)ppr;
    a2.att = (__half*)patt;
    a2.state_f32 = state;
    a2.out = (float*)d_out;

    cvt_w_kernel<<<768, 256>>>(cw);
    cvt_b_kernel<<<8192, 256>>>(cb);
    // Pass 1: gates a, r, r1  (12 N-bands of 128 over 1536 outputs)
    gru_gemm<1><<<dim3(12, BATCHSZ / BM), NTH, SMEM_BYTES>>>(a1);
    // Pass 2: gate c + final blend
    gru_gemm<2><<<dim3(4,  BATCHSZ / BM), NTH, SMEM_BYTES>>>(a2);
}

// round 8
// speedup vs baseline: 1.3680x; 1.1102x over previous
#include <cuda_runtime.h>
#include <cuda_fp16.h>
#include <cstdint>
#include <cstddef>

#define HID      512
#define BATCHSZ  65536
#define BM       128
#define BN       128
#define BK       64          // halves per K chunk
#define NK       24          // 1536 / 64
#define STAGES   3
#define NTH      256

// ---------------- fp16 scratch (device globals; no allocation allowed) ----------------
__device__ __align__(16) __half g_x16 [(size_t)BATCHSZ * HID];
__device__ __align__(16) __half g_s16 [(size_t)BATCHSZ * HID];
__device__ __align__(16) __half g_p16 [(size_t)BATCHSZ * HID];
__device__ __align__(16) __half g_hr16[(size_t)BATCHSZ * HID];
__device__ __align__(16) __half g_pr16[(size_t)BATCHSZ * HID];
__device__ __align__(16) __half g_w16 [12 * (size_t)HID * HID];  // [gate(a,r,r1,c)][sec(w,u,p)]
__device__ __align__(16) __half g_att [(size_t)BATCHSZ * HID];   // att gate, fp16

static __device__ __forceinline__ uint32_t smem_u32(const void* p) {
    uint32_t a;
    asm("{ .reg .u64 t; cvta.to.shared.u64 t, %1; cvt.u32.u64 %0, t; }" : "=r"(a) : "l"(p));
    return a;
}
static __device__ __forceinline__ float sigf(float x) {
    return __fdividef(1.0f, 1.0f + __expf(-x));
}
static __device__ __forceinline__ float tanhf_fast(float x) {
    return 1.0f - __fdividef(2.0f, __expf(2.0f * x) + 1.0f);
}

// ---------------- convert kernels ----------------
struct CvtW {
    const float* src[12];
    __half* dst[12];
};
__global__ void __launch_bounds__(256) cvt_w_kernel(CvtW a) {
    size_t stride = (size_t)gridDim.x * blockDim.x;
    for (size_t u = (size_t)blockIdx.x * blockDim.x + threadIdx.x; u < 786432u; u += stride) {
        int idx = (int)(u >> 16);
        size_t off = u & 65535u;
        float4 f = *((const float4*)a.src[idx] + off);
        __half2 h0 = __floats2half2_rn(f.x, f.y);
        __half2 h1 = __floats2half2_rn(f.z, f.w);
        uint2 pk = { *(uint32_t*)&h0, *(uint32_t*)&h1 };
        *((uint2*)a.dst[idx] + off) = pk;
    }
}
struct CvtB {
    const float* src[3];
    __half* dst[3];
};
#define BIG4 8388608u
__global__ void __launch_bounds__(256) cvt_b_kernel(CvtB a) {
    size_t stride = (size_t)gridDim.x * blockDim.x;
    for (size_t u = (size_t)blockIdx.x * blockDim.x + threadIdx.x; u < 3u * BIG4; u += stride) {
        int arr = (int)(u / BIG4);
        size_t off = u - (size_t)arr * BIG4;
        float4 f = *((const float4*)a.src[arr] + off);
        __half2 h0 = __floats2half2_rn(f.x, f.y);
        __half2 h1 = __floats2half2_rn(f.z, f.w);
        uint2 pk = { *(uint32_t*)&h0, *(uint32_t*)&h1 };
        *((uint2*)a.dst[arr] + off) = pk;
    }
}

// ---------------- GEMM ----------------
struct GArgs {
    const __half* A[3];        // K sections of virtual A
    const __half* B[3][3];     // [gate][sec]
    const float*  bias[3];
    const __half* s16;
    const __half* p16;
    __half* hr16;
    __half* pr16;
    __half* att;
    const float* state_f32;
    float*  out;
};

// smem: A stages [0, 3*16384), B stages [49152, 49152 + 3*16384). Total 96 KB -> 2 CTAs/SM.
#define SMEM_BYTES (STAGES * (16384 + 16384))

template <int PASS>
__global__ void __launch_bounds__(NTH, 2) gru_gemm(GArgs g) {
    extern __shared__ __align__(16) char sm[];
    const uint32_t smBase = smem_u32(sm);

    const int tid = threadIdx.x;
    const int wid = tid >> 5;
    const int lane = tid & 31;
    const int warp_m = wid & 1;      // 0..1 -> 64-row slice
    const int warp_n = wid >> 1;     // 0..3 -> 32-col slice
    const int m0 = blockIdx.y * BM;

    const int gate = (PASS == 1) ? (blockIdx.x >> 2) : 0;
    const int nInGate = (PASS == 1) ? ((blockIdx.x & 3) * BN) : (blockIdx.x * BN);

    const __half* Asec[3] = { g.A[0], g.A[1], g.A[2] };
    const __half* Bsec[3] = { g.B[gate][0], g.B[gate][1], g.B[gate][2] };

    // per stage: A 1024 16B chunks (128 rows x 8), B 1024 chunks; 8 per thread
    auto issue = [&](int ki, int stage) {
        const int sec = (ki * BK) >> 9;
        const int kin = ki * BK - sec * 512;         // halves
        const __half* Ag = Asec[sec];
        const __half* Bg = Bsec[sec];
        const uint32_t stA = smBase + stage * 16384;
        const uint32_t stB = smBase + STAGES * 16384 + stage * 16384;
#pragma unroll
        for (int i = 0; i < 8; ++i) {
            int q = tid + i * 256;
            int qq = q & 1023;
            int row = qq >> 3, kc = qq & 7;
            uint32_t soff = (uint32_t)(row * 128 + ((kc ^ (row & 7)) << 4));
            if (q < 1024) {
                const __half* ga = Ag + (size_t)(m0 + row) * HID + kin + kc * 8;
                asm volatile("cp.async.cg.shared.global [%0], [%1], 16;"
                             :: "r"(stA + soff), "l"(ga));
            } else {
                const __half* gb = Bg + (size_t)(nInGate + row) * HID + kin + kc * 8;
                asm volatile("cp.async.cg.shared.global [%0], [%1], 16;"
                             :: "r"(stB + soff), "l"(gb));
            }
        }
        asm volatile("cp.async.commit_group;");
    };

    float acc[4][4][4];
#pragma unroll
    for (int a = 0; a < 4; ++a)
#pragma unroll
        for (int b = 0; b < 4; ++b)
#pragma unroll
            for (int c = 0; c < 4; ++c) acc[a][b][c] = 0.0f;

    // ldmatrix lane geometry (validated)
    const int rlA = lane & 15;
    const int khA = lane >> 4;
    const int nbo = (lane & 7) + ((lane >> 4) << 3);
    const int khB = (lane >> 3) & 1;
    const int swA = lane & 7;
    const int swB = nbo & 7;

    issue(0, 0);
    issue(1, 1);

    for (int ki = 0; ki < NK; ++ki) {
        if (ki < NK - 1) asm volatile("cp.async.wait_group 1;");
        else             asm volatile("cp.async.wait_group 0;");
        __syncthreads();
        if (ki + 2 < NK) issue(ki + 2, (ki + 2) % STAGES);

        const int stage = ki % STAGES;
        const uint32_t stA = smBase + stage * 16384;
        const uint32_t stB = smBase + STAGES * 16384 + stage * 16384;
#pragma unroll
        for (int ks = 0; ks < 4; ++ks) {
            uint32_t af[4][4];
            uint32_t bf[2][4];
#pragma unroll
            for (int mt = 0; mt < 4; ++mt) {
                uint32_t addr = stA
                    + (uint32_t)((warp_m * 64 + mt * 16 + rlA) * 128)
                    + (uint32_t)(((ks * 2 + khA) ^ swA) << 4);
                asm volatile("ldmatrix.sync.aligned.m8n8.x4.shared.b16 {%0,%1,%2,%3}, [%4];"
                             : "=r"(af[mt][0]), "=r"(af[mt][1]), "=r"(af[mt][2]), "=r"(af[mt][3])
                             : "r"(addr));
            }
#pragma unroll
            for (int np = 0; np < 2; ++np) {
                uint32_t addr = stB
                    + (uint32_t)((warp_n * 32 + np * 16 + nbo) * 128)
                    + (uint32_t)(((ks * 2 + khB) ^ swB) << 4);
                asm volatile("ldmatrix.sync.aligned.m8n8.x4.shared.b16 {%0,%1,%2,%3}, [%4];"
                             : "=r"(bf[np][0]), "=r"(bf[np][1]), "=r"(bf[np][2]), "=r"(bf[np][3])
                             : "r"(addr));
            }
#pragma unroll
            for (int mt = 0; mt < 4; ++mt) {
#pragma unroll
                for (int nt = 0; nt < 4; ++nt) {
                    uint32_t b0 = bf[nt >> 1][(nt & 1) * 2 + 0];
                    uint32_t b1 = bf[nt >> 1][(nt & 1) * 2 + 1];
                    asm volatile(
                        "mma.sync.aligned.m16n8k16.row.col.f32.f16.f16.f32 "
                        "{%0,%1,%2,%3}, {%4,%5,%6,%7}, {%8,%9}, {%0,%1,%2,%3};"
                        : "+f"(acc[mt][nt][0]), "+f"(acc[mt][nt][1]),
                          "+f"(acc[mt][nt][2]), "+f"(acc[mt][nt][3])
                        : "r"(af[mt][0]), "r"(af[mt][1]), "r"(af[mt][2]), "r"(af[mt][3]),
                          "r"(b0), "r"(b1));
                }
            }
        }
    }

    // ---------------- epilogue ----------------
    const int lrow = lane >> 2;
    const int lcol = (lane & 3) * 2;
    const float* biasp = g.bias[gate];

    float bv[4][2];
#pragma unroll
    for (int nt = 0; nt < 4; ++nt) {
        int cg = nInGate + warp_n * 32 + nt * 8 + lcol;
        bv[nt][0] = biasp[cg];
        bv[nt][1] = biasp[cg + 1];
    }

#pragma unroll
    for (int mt = 0; mt < 4; ++mt) {
#pragma unroll
        for (int p = 0; p < 2; ++p) {
            int row = m0 + warp_m * 64 + mt * 16 + lrow + p * 8;
#pragma unroll
            for (int nt = 0; nt < 4; ++nt) {
                int cg = nInGate + warp_n * 32 + nt * 8 + lcol;
                float x0 = acc[mt][nt][p * 2 + 0] + bv[nt][0];
                float x1 = acc[mt][nt][p * 2 + 1] + bv[nt][1];
                size_t idx = (size_t)row * HID + cg;
                if (PASS == 1) {
                    float s0 = sigf(x0), s1 = sigf(x1);
                    if (gate == 0) {
                        *(__half2*)&g.att[idx] = __floats2half2_rn(s0, s1);
                    } else if (gate == 1) {
                        __half2 sv = *(const __half2*)&g.s16[idx];
                        float2 f = __half22float2(sv);
                        *(__half2*)&g.hr16[idx] = __floats2half2_rn(f.x * s0, f.y * s1);
                    } else {
                        __half2 pv = *(const __half2*)&g.p16[idx];
                        float2 f = __half22float2(pv);
                        *(__half2*)&g.pr16[idx] = __floats2half2_rn(f.x * s0, f.y * s1);
                    }
                } else {
                    float c0 = tanhf_fast(x0), c1 = tanhf_fast(x1);
                    __half2 ah = *(const __half2*)&g.att[idx];
                    float2 a = __half22float2(ah);
                    float2 st = *(const float2*)&g.state_f32[idx];
                    float2 o;
                    o.x = a.x * c0 + st.x - a.x * st.x;
                    o.y = a.y * c1 + st.y - a.y * st.y;
                    *(float2*)&g.out[idx] = o;
                }
            }
        }
    }
}

extern "C" void kernel_launch(void* const* d_in, const int* in_sizes, int n_in,
                              void* d_out, int out_size) {
    const float* inputs = (const float*)d_in[0];
    const float* state  = (const float*)d_in[1];
    const float* parent = (const float*)d_in[2];

    void *px16, *ps16, *pp16, *phr, *ppr, *pw16, *patt;
    cudaGetSymbolAddress(&px16, g_x16);
    cudaGetSymbolAddress(&ps16, g_s16);
    cudaGetSymbolAddress(&pp16, g_p16);
    cudaGetSymbolAddress(&phr,  g_hr16);
    cudaGetSymbolAddress(&ppr,  g_pr16);
    cudaGetSymbolAddress(&pw16, g_w16);
    cudaGetSymbolAddress(&patt, g_att);

    __half* w16 = (__half*)pw16;
    const size_t WSZ = (size_t)HID * HID;

    // gate order a,r,r1,c ; sec order w,u,p
    const int wIdx[4] = {3, 5, 7, 9};
    const int uIdx[4] = {11, 12, 13, 14};
    const int pIdx[4] = {15, 16, 17, 18};

    CvtW cw;
    for (int gg = 0; gg < 4; ++gg) {
        cw.src[gg * 3 + 0] = (const float*)d_in[wIdx[gg]];
        cw.src[gg * 3 + 1] = (const float*)d_in[uIdx[gg]];
        cw.src[gg * 3 + 2] = (const float*)d_in[pIdx[gg]];
        for (int s = 0; s < 3; ++s)
            cw.dst[gg * 3 + s] = w16 + (size_t)(gg * 3 + s) * WSZ;
    }
    CvtB cb;
    cb.src[0] = inputs; cb.dst[0] = (__half*)px16;
    cb.src[1] = state;  cb.dst[1] = (__half*)ps16;
    cb.src[2] = parent; cb.dst[2] = (__half*)pp16;

    cudaFuncSetAttribute(gru_gemm<1>, cudaFuncAttributeMaxDynamicSharedMemorySize, SMEM_BYTES);
    cudaFuncSetAttribute(gru_gemm<2>, cudaFuncAttributeMaxDynamicSharedMemorySize, SMEM_BYTES);

    GArgs a1 = {};
    a1.A[0] = (const __half*)px16; a1.A[1] = (const __half*)ps16; a1.A[2] = (const __half*)pp16;
    for (int gg = 0; gg < 3; ++gg)
        for (int s = 0; s < 3; ++s)
            a1.B[gg][s] = w16 + (size_t)(gg * 3 + s) * WSZ;
    a1.bias[0] = (const float*)d_in[4];
    a1.bias[1] = (const float*)d_in[6];
    a1.bias[2] = (const float*)d_in[8];
    a1.s16 = (const __half*)ps16;
    a1.p16 = (const __half*)pp16;
    a1.hr16 = (__half*)phr;
    a1.pr16 = (__half*)ppr;
    a1.att = (__half*)patt;
    a1.state_f32 = state;
    a1.out = nullptr;

    GArgs a2 = {};
    a2.A[0] = (const __half*)px16; a2.A[1] = (const __half*)phr; a2.A[2] = (const __half*)ppr;
    for (int s = 0; s < 3; ++s) {
        a2.B[0][s] = w16 + (size_t)(9 + s) * WSZ;
        a2.B[1][s] = a2.B[0][s];
        a2.B[2][s] = a2.B[0][s];
    }
    a2.bias[0] = (const float*)d_in[10];
    a2.bias[1] = a2.bias[0];
    a2.bias[2] = a2.bias[0];
    a2.s16 = (const __half*)ps16;
    a2.p16 = (const __half*)pp16;
    a2.hr16 = (__half*)phr;
    a2.pr16 = (__half*)ppr;
    a2.att = (__half*)patt;
    a2.state_f32 = state;
    a2.out = (float*)d_out;

    cvt_w_kernel<<<768, 256>>>(cw);
    cvt_b_kernel<<<8192, 256>>>(cb);
    // Pass 1: gates a, r, r1  (12 N-bands of 128 over 1536 outputs)
    gru_gemm<1><<<dim3(12, BATCHSZ / BM), NTH, SMEM_BYTES>>>(a1);
    // Pass 2: gate c + final blend
    gru_gemm<2><<<dim3(4,  BATCHSZ / BM), NTH, SMEM_BYTES>>>(a2);
}